// round 16
// baseline (speedup 1.0000x reference)
#include <cuda_runtime.h>
#include <cuda_fp16.h>
#include <math.h>
#include <stdint.h>

#define NB   32
#define SEQL 512
#define DIM  256
#define S2   514
#define NTOK (NB * S2)
#define HID  1024
#define WD   1280
#define NSTEPS 6
#define EPSF 1e-9f

static __device__ __align__(256) __half g_flat[NTOK * WD];
static __device__ __align__(256) __half g_cc[NTOK * 2 * DIM];
static __device__ __align__(256) __half g_inter[NTOK * HID];
static __device__ __align__(256) float g_contents[NTOK * HID];
static __device__ __align__(256) float g_convOut[NTOK * DIM];
static __device__ __align__(256) float g_seq[NTOK * DIM];
static __device__ float g_tsc[NTOK], g_ltp[NTOK];
static __device__ float g_active[NTOK], g_mask[NTOK], g_selp[NTOK], g_endm[NTOK];
static __device__ float g_mxbuf[2];
static __device__ __align__(256) __half g_convWt[DIM * WD];
static __device__ __align__(256) __half g_w1Wt[HID * 2 * DIM];
static __device__ __align__(256) __half g_w2Wt[HID * HID];
static __device__ __align__(256) __half g_itWt[DIM * DIM];

__device__ __forceinline__ float geluf(float x) {
    float x3 = x * x * x;
    return 0.5f * x * (1.f + tanhf(0.7978845608028654f * (x + 0.044715f * x3)));
}
__device__ __forceinline__ float blockReduceSum256(float v) {
    __shared__ float sh[33];
    int lane = threadIdx.x & 31, wid = threadIdx.x >> 5;
#pragma unroll
    for (int o = 16; o; o >>= 1) v += __shfl_down_sync(0xffffffffu, v, o);
    __syncthreads();
    if (lane == 0) sh[wid] = v;
    __syncthreads();
    if (wid == 0) {
        float t = (lane < 8) ? sh[lane] : 0.f;
#pragma unroll
        for (int o = 16; o; o >>= 1) t += __shfl_down_sync(0xffffffffu, t, o);
        if (lane == 0) sh[32] = t;
    }
    __syncthreads();
    return sh[32];
}

// ---------------- mma.sync helpers ----------------
__device__ __forceinline__ uint32_t s2u(const void* p) { return (uint32_t)__cvta_generic_to_shared(p); }
__device__ __forceinline__ void ldm4(uint32_t* r, uint32_t a) {
    asm volatile("ldmatrix.sync.aligned.m8n8.x4.shared.b16 {%0,%1,%2,%3}, [%4];"
                 : "=r"(r[0]), "=r"(r[1]), "=r"(r[2]), "=r"(r[3]) : "r"(a));
}
__device__ __forceinline__ void mma16816(float* c, const uint32_t* a, const uint32_t* b) {
    asm volatile("mma.sync.aligned.m16n8k16.row.col.f32.f16.f16.f32 "
                 "{%0,%1,%2,%3},{%4,%5,%6,%7},{%8,%9},{%0,%1,%2,%3};"
                 : "+f"(c[0]), "+f"(c[1]), "+f"(c[2]), "+f"(c[3])
                 : "r"(a[0]), "r"(a[1]), "r"(a[2]), "r"(a[3]), "r"(b[0]), "r"(b[1]));
}
__device__ __forceinline__ void cpasync16(uint32_t dst, const void* src, int srcsize) {
    asm volatile("cp.async.cg.shared.global [%0], [%1], 16, %2;"
                 :: "r"(dst), "l"(src), "r"(srcsize) : "memory");
}

#define ROWB 144
#define STG_S 36864
#define SMEM_S (3 * STG_S)     // 110592, 2 CTAs/SM

// shared 128x128 / 256-thread mainloop, 3-stage cp.async
__device__ __forceinline__ void gemm_main_s(
    float acc[4][4][4], const __half* __restrict__ A, int lda,
    const __half* __restrict__ B, int M, int K, int bm, int bn,
    uint32_t sbase, int tid, int m0, int n0w, int lane)
{
#pragma unroll
    for (int i = 0; i < 4; i++)
#pragma unroll
        for (int j = 0; j < 4; j++)
#pragma unroll
            for (int e = 0; e < 4; e++) acc[i][j][e] = 0.f;

    const int NK = K >> 6;
    auto fill = [&](int st, int kt) {
        int k0 = kt << 6;
#pragma unroll
        for (int q = 0; q < 8; q++) {
            int u = tid + q * 256;
            const __half* src;
            uint32_t dst;
            int sz = 16;
            if (u < 1024) {
                int r = u >> 3, c = u & 7;
                int gr = bm + r;
                if (gr >= M) { gr = 0; sz = 0; }
                src = A + (size_t)gr * lda + k0 + c * 8;
                dst = sbase + st * STG_S + r * ROWB + c * 16;
            } else {
                int v = u - 1024;
                int r = v >> 3, c = v & 7;
                src = B + (size_t)(bn + r) * K + k0 + c * 8;
                dst = sbase + st * STG_S + 18432 + r * ROWB + c * 16;
            }
            cpasync16(dst, src, sz);
        }
        asm volatile("cp.async.commit_group;" ::: "memory");
    };

    fill(0, 0);
    fill(1, 1);
    for (int kt = 0; kt < NK; kt++) {
        if (kt + 2 < NK) {
            fill((kt + 2) % 3, kt + 2);
            asm volatile("cp.async.wait_group 2;" ::: "memory");
        } else if (kt + 1 < NK) {
            asm volatile("cp.async.wait_group 1;" ::: "memory");
        } else {
            asm volatile("cp.async.wait_group 0;" ::: "memory");
        }
        __syncthreads();
        const uint32_t sA = sbase + (kt % 3) * STG_S;
        const uint32_t sB = sA + 18432;
#pragma unroll
        for (int kh = 0; kh < 4; kh++) {
            uint32_t a[4][4], bfr[2][4];
            int aoff = (m0 + (lane & 15)) * ROWB + kh * 32 + (lane >> 4) * 16;
            int boff = (n0w + ((lane & 7) | ((lane >> 1) & 8))) * ROWB
                       + kh * 32 + ((lane >> 3) & 1) * 16;
#pragma unroll
            for (int nt = 0; nt < 2; nt++)
                ldm4(bfr[nt], sB + boff + nt * 16 * ROWB);
#pragma unroll
            for (int mi = 0; mi < 4; mi++) ldm4(a[mi], sA + aoff + mi * 16 * ROWB);
#pragma unroll
            for (int mi = 0; mi < 4; mi++)
#pragma unroll
                for (int fi = 0; fi < 4; fi++)
                    mma16816(acc[mi][fi], a[mi], &bfr[fi >> 1][(fi & 1) * 2]);
        }
        __syncthreads();
    }
}

// generic small GEMM (itW init): fp32 out + bias
__global__ __launch_bounds__(256, 2) void mma_gemm_s(
    const __half* __restrict__ A, int lda, const __half* __restrict__ B,
    const float* __restrict__ bias, float* __restrict__ C, int ldc, int M, int K)
{
    extern __shared__ char smem[];
    const uint32_t sbase = s2u(smem);
    const int tid = threadIdx.x, w = tid >> 5, lane = tid & 31;
    const int bm = blockIdx.y * 128, bn = blockIdx.x * 128;
    const int m0 = (w & 1) * 64, n0w = (w >> 1) * 32;
    float acc[4][4][4];
    gemm_main_s(acc, A, lda, B, M, K, bm, bn, sbase, tid, m0, n0w, lane);
    int tq = lane >> 2, tr = lane & 3;
#pragma unroll
    for (int mi = 0; mi < 4; mi++)
#pragma unroll
        for (int fi = 0; fi < 4; fi++) {
            int col = bn + n0w + fi * 8 + tr * 2;
            float b0 = bias[col], b1 = bias[col + 1];
#pragma unroll
            for (int half = 0; half < 2; half++) {
                int row = bm + m0 + mi * 16 + tq + half * 8;
                if (row >= M) continue;
                *(float2*)(C + (size_t)row * ldc + col) =
                    make_float2(acc[mi][fi][half * 2 + 0] + b0,
                                acc[mi][fi][half * 2 + 1] + b1);
            }
        }
}

// fused wave: x in [0,8) = w1 N-tiles (gelu -> half g_inter); x in [8,10) = conv score tiles
__global__ __launch_bounds__(256, 2) void mma_gemm_w1conv(
    const float* __restrict__ w1b, const float* __restrict__ convb,
    const float* __restrict__ scW)
{
    extern __shared__ char smem[];
    const uint32_t sbase = s2u(smem);
    const int tid = threadIdx.x, w = tid >> 5, lane = tid & 31;
    const int bm = blockIdx.y * 128;
    const int m0 = (w & 1) * 64, n0w = (w >> 1) * 32;
    const bool isConv = (blockIdx.x >= 8);
    const int bn = isConv ? (blockIdx.x - 8) * 128 : blockIdx.x * 128;
    const __half* A = isConv ? g_flat : g_cc;
    const __half* B = isConv ? g_convWt : g_w1Wt;
    const int K = isConv ? WD : 2 * DIM;

    float acc[4][4][4];
    gemm_main_s(acc, A, K, B, NTOK, K, bm, bn, sbase, tid, m0, n0w, lane);

    int tq = lane >> 2, tr = lane & 3;
    if (isConv) {
        float* srow = (float*)smem;
        if (tid < 128) srow[tid] = 0.f;
        __syncthreads();
#pragma unroll
        for (int mi = 0; mi < 4; mi++)
#pragma unroll
            for (int half = 0; half < 2; half++) {
                int rl = m0 + mi * 16 + tq + half * 8;
                float s = 0.f;
#pragma unroll
                for (int fi = 0; fi < 4; fi++) {
                    int col = bn + n0w + fi * 8 + tr * 2;
                    float v0 = geluf(acc[mi][fi][half * 2 + 0] + convb[col]);
                    float v1 = geluf(acc[mi][fi][half * 2 + 1] + convb[col + 1]);
                    s += v0 * scW[col] + v1 * scW[col + 1];
                }
                atomicAdd(&srow[rl], s);
            }
        __syncthreads();
        if (tid < 128) {
            int gr = bm + tid;
            if (gr < NTOK) atomicAdd(&g_tsc[gr], srow[tid]);
        }
    } else {
#pragma unroll
        for (int mi = 0; mi < 4; mi++)
#pragma unroll
            for (int fi = 0; fi < 4; fi++) {
                int col = bn + n0w + fi * 8 + tr * 2;
                float b0 = w1b[col], b1 = w1b[col + 1];
#pragma unroll
                for (int half = 0; half < 2; half++) {
                    int row = bm + m0 + mi * 16 + tq + half * 8;
                    if (row >= NTOK) continue;
                    ushort2 h;
                    h.x = __half_as_ushort(__float2half_rn(geluf(acc[mi][fi][half * 2 + 0] + b0)));
                    h.y = __half_as_ushort(__float2half_rn(geluf(acc[mi][fi][half * 2 + 1] + b1)));
                    *(ushort2*)(g_inter + (size_t)row * HID + col) = h;
                }
            }
    }
}

// w2 GEMM + (x==0) tsc max preamble
__global__ __launch_bounds__(256, 2) void mma_gemm_w2(
    const float* __restrict__ w2b, int mxslot)
{
    extern __shared__ char smem[];
    const uint32_t sbase = s2u(smem);
    const int tid = threadIdx.x, w = tid >> 5, lane = tid & 31;
    const int bm = blockIdx.y * 128, bn = blockIdx.x * 128;
    const int m0 = (w & 1) * 64, n0w = (w >> 1) * 32;

    if (blockIdx.x == 0 && tid < 128) {
        int gr = bm + tid;
        if (gr < NTOK)
            atomicMax((unsigned int*)&g_mxbuf[mxslot],
                      __float_as_uint(fmaxf(g_tsc[gr], 0.f)));
    }

    float acc[4][4][4];
    gemm_main_s(acc, g_inter, HID, g_w2Wt, NTOK, HID, bm, bn, sbase, tid, m0, n0w, lane);
    int tq = lane >> 2, tr = lane & 3;
#pragma unroll
    for (int mi = 0; mi < 4; mi++)
#pragma unroll
        for (int fi = 0; fi < 4; fi++) {
            int col = bn + n0w + fi * 8 + tr * 2;
            float b0 = w2b[col], b1 = w2b[col + 1];
#pragma unroll
            for (int half = 0; half < 2; half++) {
                int row = bm + m0 + mi * 16 + tq + half * 8;
                if (row >= NTOK) continue;
                *(float2*)(g_contents + (size_t)row * HID + col) =
                    make_float2(acc[mi][fi][half * 2 + 0] + b0,
                                acc[mi][fi][half * 2 + 1] + b1);
            }
        }
}

// ---------------- init kernels ----------------
__global__ void init_masks_kernel(const float* __restrict__ im) {
    int idx = blockIdx.x * blockDim.x + threadIdx.x;
    if (idx < 2) g_mxbuf[idx] = 0.f;
    if (idx >= NTOK) return;
    int b = idx / S2, i = idx % S2;
    auto mask_yes = [&](int j) -> float { return (j <= 1) ? 1.f : im[b * SEQL + (j - 2)]; };
    auto mask_no_end = [&](int j) -> float {
        if (j == 0) return 1.f;
        if (j <= SEQL) return im[b * SEQL + (j - 1)];
        return 0.f;
    };
    float my = mask_yes(i), mne = mask_no_end(i);
    float mask_no_start = (i == 0) ? 0.f : my;
    float last_token = (i < S2 - 1) ? (mask_yes(i + 1) - mask_no_end(i + 1)) : 0.f;
    g_mask[idx] = my;
    g_endm[idx] = my - mne;
    g_selp[idx] = mask_no_start * mne * (1.f - last_token);
    g_active[idx] = my;
    g_ltp[idx] = 0.f;
}

__global__ void init_seqpre_kernel(const float* __restrict__ seqin,
                                   const float* __restrict__ START,
                                   const float* __restrict__ END) {
    int idx = blockIdx.x * blockDim.x + threadIdx.x;
    if (idx >= NTOK * DIM) return;
    int tok = idx / DIM, f = idx % DIM;
    int b = tok / S2, i = tok % S2;
    float base;
    if (i == 0)          base = START[f];
    else if (i <= SEQL)  base = seqin[((size_t)b * SEQL + (i - 1)) * DIM + f];
    else                 base = 0.f;
    float e = g_endm[tok];
    float x = e * END[f] + (1.f - e) * base;
    g_cc[(size_t)tok * (2 * DIM) + f] = __float2half_rn(x);
}

__global__ void ln_init_kernel(const float* __restrict__ lng, const float* __restrict__ lnb) {
    int tok = blockIdx.x, f = threadIdx.x;
    float x = g_convOut[(size_t)tok * DIM + f];
    float mean = blockReduceSum256(x) * (1.f / DIM);
    float d = x - mean;
    float r = rsqrtf(blockReduceSum256(d * d) * (1.f / DIM) + 1e-5f);
    g_seq[(size_t)tok * DIM + f] = (d * r * lng[f] + lnb[f]) * g_mask[tok];
}

__global__ void pack_all(const float* __restrict__ Wit, __half* __restrict__ Tit,
                         const float* __restrict__ Wcv, __half* __restrict__ Tcv,
                         const float* __restrict__ W1,  __half* __restrict__ T1,
                         const float* __restrict__ W2,  __half* __restrict__ T2) {
    int i = blockIdx.x * blockDim.x + threadIdx.x;
    const int n_it = DIM * DIM;
    const int n_cv = DIM * WD;
    const int n_w1 = HID * 2 * DIM;
    const int n_w2 = HID * HID;
    if (i < n_it) {
        int n = i / DIM, k = i % DIM;
        Tit[i] = __float2half_rn(Wit[(size_t)k * DIM + n]);
    } else if (i < n_it + n_cv) {
        int j = i - n_it;
        int n = j / WD, k = j % WD;
        Tcv[j] = __float2half_rn(Wcv[(size_t)k * DIM + n]);
    } else if (i < n_it + n_cv + n_w1) {
        int j = i - n_it - n_cv;
        int n = j / (2 * DIM), k = j % (2 * DIM);
        T1[j] = __float2half_rn(W1[(size_t)k * HID + n]);
    } else {
        int j = i - n_it - n_cv - n_w1;
        if (j >= n_w2) return;
        int n = j / HID, k = j % HID;
        T2[j] = __float2half_rn(W2[(size_t)k * HID + n]);
    }
}

// ---------------- scalar-per-feature scan (also seeds g_tsc = scb) ----------------
__global__ void scan_kernel(const float* __restrict__ yes_t, const float* __restrict__ no_t,
                            const float* __restrict__ scb) {
    int gid = blockIdx.x * blockDim.x + threadIdx.x;
    float scb0 = scb[0];
    for (int t = gid; t < NTOK; t += NB * 4 * 128) g_tsc[t] = scb0;
    int bid = blockIdx.x;
    int dir = bid & 1;
    int fh  = (bid >> 1) & 1;
    int b   = bid >> 2;
    int f   = fh * 128 + threadIdx.x;
    float yf = yes_t[f], nf = no_t[f];
    if (dir == 0) {
        float l1 = 0.f, l2 = 0.f, lc = 0.f;
        for (int i = 0; i < S2; i++) {
            int tok = b * S2 + i;
            float a = g_active[tok], m = g_mask[tok], lt = g_ltp[tok];
            float w = a * m * m, c = 1.f - a * m + EPSF;
            float sv = g_seq[(size_t)tok * DIM + f];
            float base = sv + lt * yf + (1.f - lt) * nf;
            size_t fl = (size_t)tok * WD;
            g_flat[fl + 0 * DIM + f] = __float2half_rn(l2);
            g_flat[fl + 1 * DIM + f] = __float2half_rn(l1);
            size_t cp = (size_t)tok * 2 * DIM;
            g_cc[cp + f]       = __float2half_rn(lc);
            g_cc[cp + DIM + f] = __float2half_rn(sv);
            float nl2 = w * l1 + c * l2;
            l1 = w * base + c * l1;
            lc = w * sv + c * lc;
            l2 = nl2;
        }
    } else {
        float r1 = 0.f, r2 = 0.f;
        for (int i = S2 - 1; i >= 0; i--) {
            int tok = b * S2 + i;
            float a = g_active[tok], m = g_mask[tok], lt = g_ltp[tok];
            float w = a * m * m, c = 1.f - a * m + EPSF;
            float sv = g_seq[(size_t)tok * DIM + f];
            float base = sv + lt * yf + (1.f - lt) * nf;
            size_t fl = (size_t)tok * WD;
            g_flat[fl + 2 * DIM + f] = __float2half_rn(base);
            g_flat[fl + 3 * DIM + f] = __float2half_rn(r1);
            g_flat[fl + 4 * DIM + f] = __float2half_rn(r2);
            float nr2 = w * r1 + c * r2;
            r1 = w * base + c * r1;
            r2 = nr2;
        }
    }
}

// ---------------- merged combine + deact ----------------
__global__ void combine_deact_kernel(const float* __restrict__ lng,
                                     const float* __restrict__ lnb,
                                     int mxslot, float* __restrict__ out) {
    if (blockIdx.x < NTOK) {
        int tok = blockIdx.x, f = threadIdx.x;
        const float* ct = g_contents + (size_t)tok * HID;
        size_t cp = (size_t)tok * 2 * DIM;
        float lc = __half2float(g_cc[cp + f]);
        float sv = g_seq[(size_t)tok * DIM + f];
        float g0 = 1.f / (1.f + expf(-ct[0 * DIM + f]));
        float g1 = 1.f / (1.f + expf(-ct[1 * DIM + f]));
        float g2 = 1.f / (1.f + expf(-ct[2 * DIM + f]));
        float y = g0 * lc + g1 * sv + g2 * ct[3 * DIM + f];
        float mean = blockReduceSum256(y) * (1.f / DIM);
        float d = y - mean;
        float r = rsqrtf(blockReduceSum256(d * d) * (1.f / DIM) + 1e-5f);
        float comp = d * r * lng[f] + lnb[f];
        float mx = g_mxbuf[mxslot];
        float et = expf(g_tsc[tok] - mx) * g_selp[tok];
        float tp = et / (et + expf(-mx) + EPSF);
        float res = (tp * comp + (1.f - tp) * sv) * g_mask[tok];
        g_seq[(size_t)tok * DIM + f] = res;
        if (out) out[(size_t)tok * DIM + f] = res;
    } else {
        __shared__ float s_a[S2], s_m[S2], s_tp[S2];
        int b = blockIdx.x - NTOK;
        float mx = g_mxbuf[mxslot];
        if (b == 0 && threadIdx.x == 0) g_mxbuf[mxslot ^ 1] = 0.f;
        float en = expf(-mx);
        for (int i = threadIdx.x; i < S2; i += blockDim.x) {
            int tok = b * S2 + i;
            s_a[i] = g_active[tok]; s_m[i] = g_mask[tok];
            float et = expf(g_tsc[tok] - mx) * g_selp[tok];
            s_tp[i] = et / (et + en + EPSF);
        }
        __syncthreads();
        if (threadIdx.x == 0) {
            float dacc = 0.f;
            for (int j = S2 - 1; j >= 0; j--) {
                float a = s_a[j], m = s_m[j], tp = s_tp[j];
                float de = a * m * m * dacc;
                s_a[j] = fminf(fmaxf(a * (1.f - de), 0.f), 1.f) * m;
                dacc = tp + (1.f - a * m + EPSF) * dacc;
            }
        }
        __syncthreads();
        for (int i = threadIdx.x; i < S2; i += blockDim.x) {
            int tok = b * S2 + i;
            g_active[tok] = s_a[i];
            g_ltp[tok]    = s_tp[i];
        }
    }
}

// ---------------- launch ----------------
extern "C" void kernel_launch(void* const* d_in, const int* in_sizes, int n_in,
                              void* d_out, int out_size) {
    const float* sequence   = (const float*)d_in[0];
    const float* input_mask = (const float*)d_in[1];
    const float* START = (const float*)d_in[2];
    const float* END   = (const float*)d_in[3];
    const float* yes_t = (const float*)d_in[4];
    const float* no_t  = (const float*)d_in[5];
    const float* convW = (const float*)d_in[6];
    const float* convb = (const float*)d_in[7];
    const float* scW   = (const float*)d_in[8];
    const float* scb   = (const float*)d_in[9];
    const float* itW   = (const float*)d_in[10];
    const float* itb   = (const float*)d_in[11];
    const float* w1W   = (const float*)d_in[12];
    const float* w1b   = (const float*)d_in[13];
    const float* w2W   = (const float*)d_in[14];
    const float* w2b   = (const float*)d_in[15];
    const float* lng   = (const float*)d_in[16];
    const float* lnb   = (const float*)d_in[17];
    float* out = (float*)d_out;

    __half *p_cc, *p_convWt, *p_w1Wt, *p_w2Wt, *p_itWt;
    float *p_convOut;
    cudaGetSymbolAddress((void**)&p_cc, g_cc);
    cudaGetSymbolAddress((void**)&p_convOut, g_convOut);
    cudaGetSymbolAddress((void**)&p_convWt, g_convWt);
    cudaGetSymbolAddress((void**)&p_w1Wt, g_w1Wt);
    cudaGetSymbolAddress((void**)&p_w2Wt, g_w2Wt);
    cudaGetSymbolAddress((void**)&p_itWt, g_itWt);

    cudaFuncSetAttribute(mma_gemm_s, cudaFuncAttributeMaxDynamicSharedMemorySize, SMEM_S);
    cudaFuncSetAttribute(mma_gemm_w1conv, cudaFuncAttributeMaxDynamicSharedMemorySize, SMEM_S);
    cudaFuncSetAttribute(mma_gemm_w2, cudaFuncAttributeMaxDynamicSharedMemorySize, SMEM_S);

    const int THR = 256;
    const int GM = (NTOK + 127) / 128;   // 129
    const int PACK_N = DIM * DIM + DIM * WD + HID * 2 * DIM + HID * HID;

    init_masks_kernel<<<(NTOK + THR - 1) / THR, THR>>>(input_mask);
    init_seqpre_kernel<<<(NTOK * DIM + THR - 1) / THR, THR>>>(sequence, START, END);
    pack_all<<<(PACK_N + THR - 1) / THR, THR>>>(itW, p_itWt, convW, p_convWt,
                                                w1W, p_w1Wt, w2W, p_w2Wt);

    mma_gemm_s<<<dim3(2, GM), 256, SMEM_S>>>(p_cc, 2 * DIM, p_itWt, itb,
                                             p_convOut, DIM, NTOK, DIM);
    ln_init_kernel<<<NTOK, DIM>>>(lng, lnb);

    for (int s = 0; s < NSTEPS; s++) {
        int slot = s & 1;
        scan_kernel<<<NB * 4, 128>>>(yes_t, no_t, scb);
        mma_gemm_w1conv<<<dim3(10, GM), 256, SMEM_S>>>(w1b, convb, scW);
        mma_gemm_w2<<<dim3(8, GM), 256, SMEM_S>>>(w2b, slot);
        combine_deact_kernel<<<NTOK + NB, 256>>>(lng, lnb, slot,
                                                 (s == NSTEPS - 1) ? out : nullptr);
    }
}

// round 17
// speedup vs baseline: 1.0861x; 1.0861x over previous
#include <cuda_runtime.h>
#include <cuda_fp16.h>
#include <math.h>
#include <stdint.h>

#define NB   32
#define SEQL 512
#define DIM  256
#define S2   514
#define NTOK (NB * S2)
#define HID  1024
#define WD   1280
#define NSTEPS 6
#define EPSF 1e-9f

static __device__ __align__(256) __half g_flat[NTOK * WD];
static __device__ __align__(256) __half g_cc[NTOK * 2 * DIM];
static __device__ __align__(256) __half g_inter[NTOK * HID];
static __device__ __align__(256) __half g_contents[NTOK * HID];   // fp16 now
static __device__ __align__(256) float g_convOut[NTOK * DIM];
static __device__ __align__(256) float g_seq[NTOK * DIM];
static __device__ float g_tsc[NTOK], g_ltp[NTOK];
static __device__ float g_active[NTOK], g_mask[NTOK], g_selp[NTOK], g_endm[NTOK];
static __device__ float g_mxbuf[2];
static __device__ __align__(256) __half g_convWt[DIM * WD];
static __device__ __align__(256) __half g_w1Wt[HID * 2 * DIM];
static __device__ __align__(256) __half g_w2Wt[HID * HID];
static __device__ __align__(256) __half g_itWt[DIM * DIM];

__device__ __forceinline__ float geluf(float x) {
    float x3 = x * x * x;
    return 0.5f * x * (1.f + tanhf(0.7978845608028654f * (x + 0.044715f * x3)));
}
__device__ __forceinline__ float blockReduceSum256(float v) {
    __shared__ float sh[33];
    int lane = threadIdx.x & 31, wid = threadIdx.x >> 5;
#pragma unroll
    for (int o = 16; o; o >>= 1) v += __shfl_down_sync(0xffffffffu, v, o);
    __syncthreads();
    if (lane == 0) sh[wid] = v;
    __syncthreads();
    if (wid == 0) {
        float t = (lane < 8) ? sh[lane] : 0.f;
#pragma unroll
        for (int o = 16; o; o >>= 1) t += __shfl_down_sync(0xffffffffu, t, o);
        if (lane == 0) sh[32] = t;
    }
    __syncthreads();
    return sh[32];
}

// ---------------- mma.sync helpers ----------------
__device__ __forceinline__ uint32_t s2u(const void* p) { return (uint32_t)__cvta_generic_to_shared(p); }
__device__ __forceinline__ void ldm4(uint32_t* r, uint32_t a) {
    asm volatile("ldmatrix.sync.aligned.m8n8.x4.shared.b16 {%0,%1,%2,%3}, [%4];"
                 : "=r"(r[0]), "=r"(r[1]), "=r"(r[2]), "=r"(r[3]) : "r"(a));
}
__device__ __forceinline__ void mma16816(float* c, const uint32_t* a, const uint32_t* b) {
    asm volatile("mma.sync.aligned.m16n8k16.row.col.f32.f16.f16.f32 "
                 "{%0,%1,%2,%3},{%4,%5,%6,%7},{%8,%9},{%0,%1,%2,%3};"
                 : "+f"(c[0]), "+f"(c[1]), "+f"(c[2]), "+f"(c[3])
                 : "r"(a[0]), "r"(a[1]), "r"(a[2]), "r"(a[3]), "r"(b[0]), "r"(b[1]));
}
__device__ __forceinline__ void cpasync16(uint32_t dst, const void* src, int srcsize) {
    asm volatile("cp.async.cg.shared.global [%0], [%1], 16, %2;"
                 :: "r"(dst), "l"(src), "r"(srcsize) : "memory");
}

#define ROWB 144

// ============ small-tile GEMM: 128x128 CTA, 256 threads, 2 CTAs/SM ============
#define STG_S 36864
#define SMEM_S (3 * STG_S)     // 110592
template <int ACT, int OUTP>
__global__ __launch_bounds__(256, 2) void mma_gemm_s(
    const __half* __restrict__ A, int lda, const __half* __restrict__ B,
    const float* __restrict__ bias, void* __restrict__ C, int ldc, int M, int K)
{
    extern __shared__ char smem[];
    const uint32_t sbase = s2u(smem);
    const int tid = threadIdx.x, w = tid >> 5, lane = tid & 31;
    const int bm = blockIdx.y * 128, bn = blockIdx.x * 128;
    const int m0 = (w & 1) * 64, n0w = (w >> 1) * 32;
    const int NK = K >> 6;

    float acc[4][4][4];
#pragma unroll
    for (int i = 0; i < 4; i++)
#pragma unroll
        for (int j = 0; j < 4; j++)
#pragma unroll
            for (int e = 0; e < 4; e++) acc[i][j][e] = 0.f;

    auto fill = [&](int st, int kt) {
        int k0 = kt << 6;
#pragma unroll
        for (int q = 0; q < 8; q++) {
            int u = tid + q * 256;
            const __half* src;
            uint32_t dst;
            int sz = 16;
            if (u < 1024) {
                int r = u >> 3, c = u & 7;
                int gr = bm + r;
                if (gr >= M) { gr = 0; sz = 0; }
                src = A + (size_t)gr * lda + k0 + c * 8;
                dst = sbase + st * STG_S + r * ROWB + c * 16;
            } else {
                int v = u - 1024;
                int r = v >> 3, c = v & 7;
                src = B + (size_t)(bn + r) * K + k0 + c * 8;
                dst = sbase + st * STG_S + 18432 + r * ROWB + c * 16;
            }
            cpasync16(dst, src, sz);
        }
        asm volatile("cp.async.commit_group;" ::: "memory");
    };

    fill(0, 0);
    fill(1, 1);
    for (int kt = 0; kt < NK; kt++) {
        if (kt + 2 < NK) {
            fill((kt + 2) % 3, kt + 2);
            asm volatile("cp.async.wait_group 2;" ::: "memory");
        } else if (kt + 1 < NK) {
            asm volatile("cp.async.wait_group 1;" ::: "memory");
        } else {
            asm volatile("cp.async.wait_group 0;" ::: "memory");
        }
        __syncthreads();
        const uint32_t sA = sbase + (kt % 3) * STG_S;
        const uint32_t sB = sA + 18432;
#pragma unroll
        for (int kh = 0; kh < 4; kh++) {
            uint32_t a[4][4], bfr[2][4];
            int aoff = (m0 + (lane & 15)) * ROWB + kh * 32 + (lane >> 4) * 16;
            int boff = (n0w + ((lane & 7) | ((lane >> 1) & 8))) * ROWB
                       + kh * 32 + ((lane >> 3) & 1) * 16;
#pragma unroll
            for (int nt = 0; nt < 2; nt++)
                ldm4(bfr[nt], sB + boff + nt * 16 * ROWB);
#pragma unroll
            for (int mi = 0; mi < 4; mi++) ldm4(a[mi], sA + aoff + mi * 16 * ROWB);
#pragma unroll
            for (int mi = 0; mi < 4; mi++)
#pragma unroll
                for (int fi = 0; fi < 4; fi++)
                    mma16816(acc[mi][fi], a[mi], &bfr[fi >> 1][(fi & 1) * 2]);
        }
        __syncthreads();
    }

    int tq = lane >> 2, tr = lane & 3;
#pragma unroll
    for (int mi = 0; mi < 4; mi++)
#pragma unroll
        for (int fi = 0; fi < 4; fi++) {
            int col = bn + n0w + fi * 8 + tr * 2;
            float b0 = bias[col], b1 = bias[col + 1];
#pragma unroll
            for (int half = 0; half < 2; half++) {
                int row = bm + m0 + mi * 16 + tq + half * 8;
                if (row >= M) continue;
                float v0 = acc[mi][fi][half * 2 + 0] + b0;
                float v1 = acc[mi][fi][half * 2 + 1] + b1;
                if (ACT) { v0 = geluf(v0); v1 = geluf(v1); }
                if (OUTP) {
                    ushort2 h;
                    h.x = __half_as_ushort(__float2half_rn(v0));
                    h.y = __half_as_ushort(__float2half_rn(v1));
                    *(ushort2*)((__half*)C + (size_t)row * ldc + col) = h;
                } else {
                    *(float2*)((float*)C + (size_t)row * ldc + col) = make_float2(v0, v1);
                }
            }
        }
}

// ============ conv+score GEMM: 128x256 CTA, 512 threads ============
#define STG_B 55296
#define SMEM_B (3 * STG_B)     // 165888
__global__ __launch_bounds__(512, 1) void mma_gemm_score(
    const float* __restrict__ convb, const float* __restrict__ scW,
    const float* __restrict__ scb, int mxslot)
{
    extern __shared__ char smem[];
    const uint32_t sbase = s2u(smem);
    const int tid = threadIdx.x, w = tid >> 5, lane = tid & 31;
    const int bm = blockIdx.y * 128;
    const int m0 = (w & 1) * 64, n0w = (w >> 1) * 32;
    const int K = WD, NK = K >> 6;
    const __half* A = g_flat;
    const __half* B = g_convWt;

    float acc[4][4][4];
#pragma unroll
    for (int i = 0; i < 4; i++)
#pragma unroll
        for (int j = 0; j < 4; j++)
#pragma unroll
            for (int e = 0; e < 4; e++) acc[i][j][e] = 0.f;

    auto fill = [&](int st, int kt) {
        int k0 = kt << 6;
#pragma unroll
        for (int q = 0; q < 6; q++) {
            int u = tid + q * 512;
            const __half* src;
            uint32_t dst;
            int sz = 16;
            if (u < 1024) {
                int r = u >> 3, c = u & 7;
                int gr = bm + r;
                if (gr >= NTOK) { gr = 0; sz = 0; }
                src = A + (size_t)gr * WD + k0 + c * 8;
                dst = sbase + st * STG_B + r * ROWB + c * 16;
            } else {
                int v = u - 1024;
                int r = (v >> 3) & 255, c = v & 7;
                src = B + (size_t)r * K + k0 + c * 8;
                dst = sbase + st * STG_B + 18432 + r * ROWB + c * 16;
            }
            cpasync16(dst, src, sz);
        }
        asm volatile("cp.async.commit_group;" ::: "memory");
    };

    fill(0, 0);
    fill(1, 1);
    for (int kt = 0; kt < NK; kt++) {
        if (kt + 2 < NK) {
            fill((kt + 2) % 3, kt + 2);
            asm volatile("cp.async.wait_group 2;" ::: "memory");
        } else if (kt + 1 < NK) {
            asm volatile("cp.async.wait_group 1;" ::: "memory");
        } else {
            asm volatile("cp.async.wait_group 0;" ::: "memory");
        }
        __syncthreads();
        const uint32_t sA = sbase + (kt % 3) * STG_B;
        const uint32_t sB = sA + 18432;
#pragma unroll
        for (int kh = 0; kh < 4; kh++) {
            uint32_t a[4][4], bfr[2][4];
            int aoff = (m0 + (lane & 15)) * ROWB + kh * 32 + (lane >> 4) * 16;
            int boff = (n0w + ((lane & 7) | ((lane >> 1) & 8))) * ROWB
                       + kh * 32 + ((lane >> 3) & 1) * 16;
#pragma unroll
            for (int nt = 0; nt < 2; nt++)
                ldm4(bfr[nt], sB + boff + nt * 16 * ROWB);
#pragma unroll
            for (int mi = 0; mi < 4; mi++) ldm4(a[mi], sA + aoff + mi * 16 * ROWB);
#pragma unroll
            for (int mi = 0; mi < 4; mi++)
#pragma unroll
                for (int fi = 0; fi < 4; fi++)
                    mma16816(acc[mi][fi], a[mi], &bfr[fi >> 1][(fi & 1) * 2]);
        }
        __syncthreads();
    }

    int tq = lane >> 2, tr = lane & 3;
    float* srow = (float*)smem;
    if (tid < 128) srow[tid] = 0.f;
    __syncthreads();
#pragma unroll
    for (int mi = 0; mi < 4; mi++)
#pragma unroll
        for (int half = 0; half < 2; half++) {
            int rl = m0 + mi * 16 + tq + half * 8;
            float s = 0.f;
#pragma unroll
            for (int fi = 0; fi < 4; fi++) {
                int col = n0w + fi * 8 + tr * 2;
                float v0 = geluf(acc[mi][fi][half * 2 + 0] + convb[col]);
                float v1 = geluf(acc[mi][fi][half * 2 + 1] + convb[col + 1]);
                s += v0 * scW[col] + v1 * scW[col + 1];
            }
            atomicAdd(&srow[rl], s);
        }
    __syncthreads();
    if (tid < 128) {
        int gr = bm + tid;
        if (gr < NTOK) {
            float t = srow[tid] + scb[0];
            g_tsc[gr] = t;
            atomicMax((unsigned int*)&g_mxbuf[mxslot], __float_as_uint(fmaxf(t, 0.f)));
        }
    }
}

// ---------------- init kernels ----------------
__global__ void init_masks_kernel(const float* __restrict__ im) {
    int idx = blockIdx.x * blockDim.x + threadIdx.x;
    if (idx < 2) g_mxbuf[idx] = 0.f;
    if (idx >= NTOK) return;
    int b = idx / S2, i = idx % S2;
    auto mask_yes = [&](int j) -> float { return (j <= 1) ? 1.f : im[b * SEQL + (j - 2)]; };
    auto mask_no_end = [&](int j) -> float {
        if (j == 0) return 1.f;
        if (j <= SEQL) return im[b * SEQL + (j - 1)];
        return 0.f;
    };
    float my = mask_yes(i), mne = mask_no_end(i);
    float mask_no_start = (i == 0) ? 0.f : my;
    float last_token = (i < S2 - 1) ? (mask_yes(i + 1) - mask_no_end(i + 1)) : 0.f;
    g_mask[idx] = my;
    g_endm[idx] = my - mne;
    g_selp[idx] = mask_no_start * mne * (1.f - last_token);
    g_active[idx] = my;
    g_ltp[idx] = 0.f;
}

__global__ void init_seqpre_kernel(const float* __restrict__ seqin,
                                   const float* __restrict__ START,
                                   const float* __restrict__ END) {
    int idx = blockIdx.x * blockDim.x + threadIdx.x;
    if (idx >= NTOK * DIM) return;
    int tok = idx / DIM, f = idx % DIM;
    int b = tok / S2, i = tok % S2;
    float base;
    if (i == 0)          base = START[f];
    else if (i <= SEQL)  base = seqin[((size_t)b * SEQL + (i - 1)) * DIM + f];
    else                 base = 0.f;
    float e = g_endm[tok];
    float x = e * END[f] + (1.f - e) * base;
    g_cc[(size_t)tok * (2 * DIM) + f] = __float2half_rn(x);
}

__global__ void ln_init_kernel(const float* __restrict__ lng, const float* __restrict__ lnb) {
    int tok = blockIdx.x, f = threadIdx.x;
    float x = g_convOut[(size_t)tok * DIM + f];
    float mean = blockReduceSum256(x) * (1.f / DIM);
    float d = x - mean;
    float r = rsqrtf(blockReduceSum256(d * d) * (1.f / DIM) + 1e-5f);
    g_seq[(size_t)tok * DIM + f] = (d * r * lng[f] + lnb[f]) * g_mask[tok];
}

__global__ void pack_all(const float* __restrict__ Wit, __half* __restrict__ Tit,
                         const float* __restrict__ Wcv, __half* __restrict__ Tcv,
                         const float* __restrict__ W1,  __half* __restrict__ T1,
                         const float* __restrict__ W2,  __half* __restrict__ T2) {
    int i = blockIdx.x * blockDim.x + threadIdx.x;
    const int n_it = DIM * DIM;
    const int n_cv = DIM * WD;
    const int n_w1 = HID * 2 * DIM;
    const int n_w2 = HID * HID;
    if (i < n_it) {
        int n = i / DIM, k = i % DIM;
        Tit[i] = __float2half_rn(Wit[(size_t)k * DIM + n]);
    } else if (i < n_it + n_cv) {
        int j = i - n_it;
        int n = j / WD, k = j % WD;
        Tcv[j] = __float2half_rn(Wcv[(size_t)k * DIM + n]);
    } else if (i < n_it + n_cv + n_w1) {
        int j = i - n_it - n_cv;
        int n = j / (2 * DIM), k = j % (2 * DIM);
        T1[j] = __float2half_rn(W1[(size_t)k * HID + n]);
    } else {
        int j = i - n_it - n_cv - n_w1;
        if (j >= n_w2) return;
        int n = j / HID, k = j % HID;
        T2[j] = __float2half_rn(W2[(size_t)k * HID + n]);
    }
}

// ---------------- scalar-per-feature scan ----------------
__global__ void scan_kernel(const float* __restrict__ yes_t, const float* __restrict__ no_t) {
    int bid = blockIdx.x;
    int dir = bid & 1;
    int fh  = (bid >> 1) & 1;
    int b   = bid >> 2;
    int f   = fh * 128 + threadIdx.x;
    float yf = yes_t[f], nf = no_t[f];
    if (dir == 0) {
        float l1 = 0.f, l2 = 0.f, lc = 0.f;
        for (int i = 0; i < S2; i++) {
            int tok = b * S2 + i;
            float a = g_active[tok], m = g_mask[tok], lt = g_ltp[tok];
            float w = a * m * m, c = 1.f - a * m + EPSF;
            float sv = g_seq[(size_t)tok * DIM + f];
            float base = sv + lt * yf + (1.f - lt) * nf;
            size_t fl = (size_t)tok * WD;
            g_flat[fl + 0 * DIM + f] = __float2half_rn(l2);
            g_flat[fl + 1 * DIM + f] = __float2half_rn(l1);
            size_t cp = (size_t)tok * 2 * DIM;
            g_cc[cp + f]       = __float2half_rn(lc);
            g_cc[cp + DIM + f] = __float2half_rn(sv);
            float nl2 = w * l1 + c * l2;
            l1 = w * base + c * l1;
            lc = w * sv + c * lc;
            l2 = nl2;
        }
    } else {
        float r1 = 0.f, r2 = 0.f;
        for (int i = S2 - 1; i >= 0; i--) {
            int tok = b * S2 + i;
            float a = g_active[tok], m = g_mask[tok], lt = g_ltp[tok];
            float w = a * m * m, c = 1.f - a * m + EPSF;
            float sv = g_seq[(size_t)tok * DIM + f];
            float base = sv + lt * yf + (1.f - lt) * nf;
            size_t fl = (size_t)tok * WD;
            g_flat[fl + 2 * DIM + f] = __float2half_rn(base);
            g_flat[fl + 3 * DIM + f] = __float2half_rn(r1);
            g_flat[fl + 4 * DIM + f] = __float2half_rn(r2);
            float nr2 = w * r1 + c * r2;
            r1 = w * base + c * r1;
            r2 = nr2;
        }
    }
}

// ---------------- merged combine + deact (contents now fp16) ----------------
__global__ void combine_deact_kernel(const float* __restrict__ lng,
                                     const float* __restrict__ lnb,
                                     int mxslot, float* __restrict__ out) {
    if (blockIdx.x < NTOK) {
        int tok = blockIdx.x, f = threadIdx.x;
        const __half* ct = g_contents + (size_t)tok * HID;
        size_t cp = (size_t)tok * 2 * DIM;
        float lc = __half2float(g_cc[cp + f]);
        float sv = g_seq[(size_t)tok * DIM + f];
        float g0 = 1.f / (1.f + expf(-__half2float(ct[0 * DIM + f])));
        float g1 = 1.f / (1.f + expf(-__half2float(ct[1 * DIM + f])));
        float g2 = 1.f / (1.f + expf(-__half2float(ct[2 * DIM + f])));
        float y = g0 * lc + g1 * sv + g2 * __half2float(ct[3 * DIM + f]);
        float mean = blockReduceSum256(y) * (1.f / DIM);
        float d = y - mean;
        float r = rsqrtf(blockReduceSum256(d * d) * (1.f / DIM) + 1e-5f);
        float comp = d * r * lng[f] + lnb[f];
        float mx = g_mxbuf[mxslot];
        float et = expf(g_tsc[tok] - mx) * g_selp[tok];
        float tp = et / (et + expf(-mx) + EPSF);
        float res = (tp * comp + (1.f - tp) * sv) * g_mask[tok];
        g_seq[(size_t)tok * DIM + f] = res;
        if (out) out[(size_t)tok * DIM + f] = res;
    } else {
        __shared__ float s_a[S2], s_m[S2], s_tp[S2];
        int b = blockIdx.x - NTOK;
        float mx = g_mxbuf[mxslot];
        if (b == 0 && threadIdx.x == 0) g_mxbuf[mxslot ^ 1] = 0.f;
        float en = expf(-mx);
        for (int i = threadIdx.x; i < S2; i += blockDim.x) {
            int tok = b * S2 + i;
            s_a[i] = g_active[tok]; s_m[i] = g_mask[tok];
            float et = expf(g_tsc[tok] - mx) * g_selp[tok];
            s_tp[i] = et / (et + en + EPSF);
        }
        __syncthreads();
        if (threadIdx.x == 0) {
            float dacc = 0.f;
            for (int j = S2 - 1; j >= 0; j--) {
                float a = s_a[j], m = s_m[j], tp = s_tp[j];
                float de = a * m * m * dacc;
                s_a[j] = fminf(fmaxf(a * (1.f - de), 0.f), 1.f) * m;
                dacc = tp + (1.f - a * m + EPSF) * dacc;
            }
        }
        __syncthreads();
        for (int i = threadIdx.x; i < S2; i += blockDim.x) {
            int tok = b * S2 + i;
            g_active[tok] = s_a[i];
            g_ltp[tok]    = s_tp[i];
        }
    }
}

// ---------------- launch ----------------
extern "C" void kernel_launch(void* const* d_in, const int* in_sizes, int n_in,
                              void* d_out, int out_size) {
    const float* sequence   = (const float*)d_in[0];
    const float* input_mask = (const float*)d_in[1];
    const float* START = (const float*)d_in[2];
    const float* END   = (const float*)d_in[3];
    const float* yes_t = (const float*)d_in[4];
    const float* no_t  = (const float*)d_in[5];
    const float* convW = (const float*)d_in[6];
    const float* convb = (const float*)d_in[7];
    const float* scW   = (const float*)d_in[8];
    const float* scb   = (const float*)d_in[9];
    const float* itW   = (const float*)d_in[10];
    const float* itb   = (const float*)d_in[11];
    const float* w1W   = (const float*)d_in[12];
    const float* w1b   = (const float*)d_in[13];
    const float* w2W   = (const float*)d_in[14];
    const float* w2b   = (const float*)d_in[15];
    const float* lng   = (const float*)d_in[16];
    const float* lnb   = (const float*)d_in[17];
    float* out = (float*)d_out;

    __half *p_cc, *p_inter, *p_contents, *p_convWt, *p_w1Wt, *p_w2Wt, *p_itWt;
    float *p_convOut;
    cudaGetSymbolAddress((void**)&p_cc, g_cc);
    cudaGetSymbolAddress((void**)&p_inter, g_inter);
    cudaGetSymbolAddress((void**)&p_contents, g_contents);
    cudaGetSymbolAddress((void**)&p_convOut, g_convOut);
    cudaGetSymbolAddress((void**)&p_convWt, g_convWt);
    cudaGetSymbolAddress((void**)&p_w1Wt, g_w1Wt);
    cudaGetSymbolAddress((void**)&p_w2Wt, g_w2Wt);
    cudaGetSymbolAddress((void**)&p_itWt, g_itWt);

    cudaFuncSetAttribute(mma_gemm_s<0,0>, cudaFuncAttributeMaxDynamicSharedMemorySize, SMEM_S);
    cudaFuncSetAttribute(mma_gemm_s<1,1>, cudaFuncAttributeMaxDynamicSharedMemorySize, SMEM_S);
    cudaFuncSetAttribute(mma_gemm_s<0,1>, cudaFuncAttributeMaxDynamicSharedMemorySize, SMEM_S);
    cudaFuncSetAttribute(mma_gemm_score, cudaFuncAttributeMaxDynamicSharedMemorySize, SMEM_B);

    const int THR = 256;
    const int GM = (NTOK + 127) / 128;   // 129
    const int PACK_N = DIM * DIM + DIM * WD + HID * 2 * DIM + HID * HID;

    init_masks_kernel<<<(NTOK + THR - 1) / THR, THR>>>(input_mask);
    init_seqpre_kernel<<<(NTOK * DIM + THR - 1) / THR, THR>>>(sequence, START, END);
    pack_all<<<(PACK_N + THR - 1) / THR, THR>>>(itW, p_itWt, convW, p_convWt,
                                                w1W, p_w1Wt, w2W, p_w2Wt);

    mma_gemm_s<0,0><<<dim3(2, GM), 256, SMEM_S>>>(p_cc, 2 * DIM, p_itWt, itb,
                                                  p_convOut, DIM, NTOK, DIM);
    ln_init_kernel<<<NTOK, DIM>>>(lng, lnb);

    for (int s = 0; s < NSTEPS; s++) {
        int slot = s & 1;
        scan_kernel<<<NB * 4, 128>>>(yes_t, no_t);
        mma_gemm_score<<<dim3(1, GM), 512, SMEM_B>>>(convb, scW, scb, slot);
        mma_gemm_s<1,1><<<dim3(8, GM), 256, SMEM_S>>>(p_cc, 2 * DIM, p_w1Wt, w1b,
                                                      p_inter, HID, NTOK, 2 * DIM);
        mma_gemm_s<0,1><<<dim3(8, GM), 256, SMEM_S>>>(p_inter, HID, p_w2Wt, w2b,
                                                      p_contents, HID, NTOK, HID);
        combine_deact_kernel<<<NTOK + NB, 256>>>(lng, lnb, slot,
                                                 (s == NSTEPS - 1) ? out : nullptr);
    }
}